// round 6
// baseline (speedup 1.0000x reference)
#include <cuda_runtime.h>

#define HID    400
#define SEQ    8192
#define DEPTH  32
#define ROW    (DEPTH * HID)       // 12800 floats per timestep slab
#define TOPF4  (HID / 4)           // 100 float4 in row 0
#define TPB    256
#define WPB    (TPB / 32)          // 8 warps (= timesteps) per block

// Per-timestep scalar scratch: s_t = softmax(h_t @ W^T + b)[0] * sigmoid(h_t @ D)
__device__ float g_scalar[SEQ];

// One warp per timestep: 4 dot products of length 400, butterfly reduce,
// lane 0 writes the scalar. Runs concurrently with the big memset.
__global__ void __launch_bounds__(TPB)
compute_kernel(const float* __restrict__ hid,
               const float* __restrict__ W,
               const float* __restrict__ b,
               const float* __restrict__ D)
{
    const int warp = threadIdx.x >> 5;
    const int lane = threadIdx.x & 31;
    const int t    = blockIdx.x * WPB + warp;

    const float4* h4 = reinterpret_cast<const float4*>(hid + (size_t)t * HID);
    const float4* W4 = reinterpret_cast<const float4*>(W);
    const float4* D4 = reinterpret_cast<const float4*>(D);

    float a0 = 0.f, a1 = 0.f, a2 = 0.f, ad = 0.f;
    #pragma unroll
    for (int k = 0; k < 4; k++) {
        int i = lane + (k << 5);
        if (i < TOPF4) {
            float4 x  = h4[i];
            float4 w0 = W4[i];
            float4 w1 = W4[TOPF4 + i];
            float4 w2 = W4[2 * TOPF4 + i];
            float4 dd = D4[i];
            a0 += x.x * w0.x + x.y * w0.y + x.z * w0.z + x.w * w0.w;
            a1 += x.x * w1.x + x.y * w1.y + x.z * w1.z + x.w * w1.w;
            a2 += x.x * w2.x + x.y * w2.y + x.z * w2.z + x.w * w2.w;
            ad += x.x * dd.x + x.y * dd.y + x.z * dd.z + x.w * dd.w;
        }
    }

    #pragma unroll
    for (int o = 16; o > 0; o >>= 1) {
        a0 += __shfl_xor_sync(0xffffffffu, a0, o);
        a1 += __shfl_xor_sync(0xffffffffu, a1, o);
        a2 += __shfl_xor_sync(0xffffffffu, a2, o);
        ad += __shfl_xor_sync(0xffffffffu, ad, o);
    }

    if (lane == 0) {
        float l0 = a0 + b[0], l1 = a1 + b[1], l2 = a2 + b[2];
        float m  = fmaxf(l0, fmaxf(l1, l2));
        float e0 = __expf(l0 - m);
        float e1 = __expf(l1 - m);
        float e2 = __expf(l2 - m);
        float p  = e0 / (e0 + e1 + e2);
        float v  = 1.f / (1.f + __expf(-ad));
        g_scalar[t] = p * v;
    }
}

// One warp per timestep: broadcast g_scalar[t] into row 0 (400 floats) of slab t.
// Rows 1..31 were zeroed by the memset node.
__global__ void __launch_bounds__(TPB)
scatter_kernel(float* __restrict__ out)
{
    const int warp = threadIdx.x >> 5;
    const int lane = threadIdx.x & 31;
    const int t    = blockIdx.x * WPB + warp;

    const float  s  = g_scalar[t];
    const float4 sv = make_float4(s, s, s, s);
    float4* o = reinterpret_cast<float4*>(out + (size_t)t * ROW);
    #pragma unroll
    for (int k = 0; k < 4; k++) {
        int i = lane + (k << 5);
        if (i < TOPF4) o[i] = sv;
    }
}

namespace {
struct Ctx {
    cudaStream_t s1;
    cudaEvent_t  ev_fork, ev_join;
    Ctx() {
        cudaStreamCreateWithFlags(&s1, cudaStreamNonBlocking);
        cudaEventCreateWithFlags(&ev_fork, cudaEventDisableTiming);
        cudaEventCreateWithFlags(&ev_join, cudaEventDisableTiming);
    }
};
Ctx ctx;  // host-side resources only; created once at process start
}

extern "C" void kernel_launch(void* const* d_in, const int* in_sizes, int n_in,
                              void* d_out, int out_size)
{
    const float* hid = (const float*)d_in[0];   // (1, 8192, 400)
    const float* W   = (const float*)d_in[1];   // (3, 400)
    const float* b   = (const float*)d_in[2];   // (3,)
    const float* D   = (const float*)d_in[3];   // (1, 400)
    float* out = (float*)d_out;                 // (1, 8192, 32, 400)

    // Fork: compute scalars on side stream, concurrent with the bulk memset.
    cudaEventRecord(ctx.ev_fork, 0);
    cudaStreamWaitEvent(ctx.s1, ctx.ev_fork, 0);
    compute_kernel<<<SEQ / WPB, TPB, 0, ctx.s1>>>(hid, W, b, D);
    cudaEventRecord(ctx.ev_join, ctx.s1);

    // Bulk zero of the whole 419 MB output on the main stream (~7.4 TB/s fill path).
    cudaMemsetAsync(out, 0, (size_t)SEQ * ROW * sizeof(float), 0);

    // Join, then overwrite row 0 of each slab (13 MB of stores).
    cudaStreamWaitEvent(0, ctx.ev_join, 0);
    scatter_kernel<<<SEQ / WPB, TPB>>>(out);
}

// round 11
// speedup vs baseline: 1.0982x; 1.0982x over previous
#include <cuda_runtime.h>

#define HID    400
#define SEQ    8192
#define DEPTH  32
#define ROW    (DEPTH * HID)       // 12800 floats per timestep slab
#define TOPF4  (HID / 4)           // 100 float4 in row 0
#define TPB    128                 // 4 warps = 4 timesteps per block
#define WPB    (TPB / 32)

// One warp per timestep: computes
//   s_t = softmax(h_t @ W^T + b)[0] * sigmoid(h_t @ D)
// and writes row 0 (400 floats) of slab t. Rows 1..31 are zeroed by the
// CONCURRENT pitched-memset node (disjoint bytes).
__global__ void __launch_bounds__(TPB)
top_kernel(const float* __restrict__ hid,
           const float* __restrict__ W,
           const float* __restrict__ b,
           const float* __restrict__ D,
           float* __restrict__ out)
{
    const int warp = threadIdx.x >> 5;
    const int lane = threadIdx.x & 31;
    const int t    = blockIdx.x * WPB + warp;

    const float4* h4 = reinterpret_cast<const float4*>(hid + (size_t)t * HID);
    const float4* W4 = reinterpret_cast<const float4*>(W);
    const float4* D4 = reinterpret_cast<const float4*>(D);

    float a0 = 0.f, a1 = 0.f, a2 = 0.f, ad = 0.f;
    #pragma unroll
    for (int k = 0; k < 4; k++) {
        int i = lane + (k << 5);
        if (i < TOPF4) {
            float4 x  = h4[i];
            float4 w0 = W4[i];
            float4 w1 = W4[TOPF4 + i];
            float4 w2 = W4[2 * TOPF4 + i];
            float4 dd = D4[i];
            a0 += x.x * w0.x + x.y * w0.y + x.z * w0.z + x.w * w0.w;
            a1 += x.x * w1.x + x.y * w1.y + x.z * w1.z + x.w * w1.w;
            a2 += x.x * w2.x + x.y * w2.y + x.z * w2.z + x.w * w2.w;
            ad += x.x * dd.x + x.y * dd.y + x.z * dd.z + x.w * dd.w;
        }
    }

    #pragma unroll
    for (int o = 16; o > 0; o >>= 1) {
        a0 += __shfl_xor_sync(0xffffffffu, a0, o);
        a1 += __shfl_xor_sync(0xffffffffu, a1, o);
        a2 += __shfl_xor_sync(0xffffffffu, a2, o);
        ad += __shfl_xor_sync(0xffffffffu, ad, o);
    }

    // Redundant per-lane epilogue (MUFU is cheap; avoids a broadcast).
    float l0 = a0 + b[0], l1 = a1 + b[1], l2 = a2 + b[2];
    float m  = fmaxf(l0, fmaxf(l1, l2));
    float e0 = __expf(l0 - m);
    float e1 = __expf(l1 - m);
    float e2 = __expf(l2 - m);
    float p  = e0 / (e0 + e1 + e2);
    float v  = 1.f / (1.f + __expf(-ad));
    float s  = p * v;

    const float4 sv = make_float4(s, s, s, s);
    float4* o = reinterpret_cast<float4*>(out + (size_t)t * ROW);
    #pragma unroll
    for (int k = 0; k < 4; k++) {
        int i = lane + (k << 5);
        if (i < TOPF4) o[i] = sv;
    }
}

namespace {
struct Ctx {
    cudaStream_t s1;
    cudaEvent_t  ev_fork, ev_join;
    Ctx() {
        cudaStreamCreateWithFlags(&s1, cudaStreamNonBlocking);
        cudaEventCreateWithFlags(&ev_fork, cudaEventDisableTiming);
        cudaEventCreateWithFlags(&ev_join, cudaEventDisableTiming);
    }
};
Ctx ctx;  // host-side stream/event resources only (no device allocations)
}

extern "C" void kernel_launch(void* const* d_in, const int* in_sizes, int n_in,
                              void* d_out, int out_size)
{
    const float* hid = (const float*)d_in[0];   // (1, 8192, 400)
    const float* W   = (const float*)d_in[1];   // (3, 400)
    const float* b   = (const float*)d_in[2];   // (3,)
    const float* D   = (const float*)d_in[3];   // (1, 400)
    float* out = (float*)d_out;                 // (1, 8192, 32, 400)

    // Fork: row-0 compute+write on side stream (bytes [0,1600) of each slab).
    cudaEventRecord(ctx.ev_fork, 0);
    cudaStreamWaitEvent(ctx.s1, ctx.ev_fork, 0);
    top_kernel<<<SEQ / WPB, TPB, 0, ctx.s1>>>(hid, W, b, D, out);
    cudaEventRecord(ctx.ev_join, ctx.s1);

    // Main stream: pitched memset zeroing ONLY rows 1..31 of every slab
    // (bytes [1600, 51200) of each slab) — disjoint from the kernel's writes,
    // so the two nodes run concurrently.
    cudaMemset2DAsync(out + HID,                      // start at row 1 of slab 0
                      (size_t)ROW * sizeof(float),    // pitch = 51200 B
                      0,
                      (size_t)(DEPTH - 1) * HID * sizeof(float),  // width = 49600 B
                      SEQ, 0);

    // Join: graph sink depends on both branches.
    cudaStreamWaitEvent(0, ctx.ev_join, 0);
}